// round 9
// baseline (speedup 1.0000x reference)
#include <cuda_runtime.h>
#include <cuda_fp16.h>

#define NC 32
#define NLEV 6
#define TOTAL 349440   // sum of res^2 over 6 levels

// Pool: [face][texel(level-major)][channel], HALF, 134 MB
__device__ __half POOLH[6ll * TOTAL * NC];
// Scratch: unfiltered pooled levels 1..5, channel-last HALF. 33.5 MB
__device__ __half SCRATCH[523776ll * NC];

__constant__ int d_offs[NLEV] = {0, 262144, 327680, 344064, 348160, 349184};

// Fused-filter per-level tables (levels 1..5), 16x16 tiles
__constant__ int   F_start[5]  = {0, 1536, 1920, 2016, 2040};   // total 2046 blocks
__constant__ int   F_inOff[5]  = {0, 393216, 491520, 516096, 522240};
__constant__ int   F_poolOff[5]= {262144, 327680, 344064, 348160, 349184};
__constant__ float F_a2[5]     = {0.00243101246f, 0.030233088f, 0.137822329f, 0.419904f, 0.96059601f}; // rough^4

// ---------------------------------------------------------------------------
// K1: transpose feature (C,6,512,512) -> pool level0 (half, channel-last)
//     AND compute level-1 avg-pool into SCRATCH (half)
// ---------------------------------------------------------------------------
__global__ void k_transpose_pool1(const float* __restrict__ feat) {
    int f = blockIdx.z;
    int x0 = blockIdx.x * 64;
    int y0 = blockIdx.y * 2;
    __shared__ float s[32 * 129];
    int tid = threadIdx.x;

    for (int i = tid; i < 32 * 32; i += 256) {
        int c = i >> 5, v = i & 31;
        int t0 = v * 4;
        int yy = y0 + (t0 >> 6), xx = x0 + (t0 & 63);
        float4 d = *(const float4*)&feat[(((size_t)c * 6 + f) * 512 + yy) * 512 + xx];
        s[c * 129 + t0 + 0] = d.x;
        s[c * 129 + t0 + 1] = d.y;
        s[c * 129 + t0 + 2] = d.z;
        s[c * 129 + t0 + 3] = d.w;
    }
    __syncthreads();

    uint4* P4 = (uint4*)POOLH;   // one uint4 = 8 half channels
    for (int i = tid; i < 512; i += 256) {
        int t = i >> 2, q = i & 3;
        int yy = y0 + (t >> 6), xx = x0 + (t & 63);
        const float* sp = &s[(8 * q) * 129 + t];
        __half2 h0 = __floats2half2_rn(sp[0],       sp[129]);
        __half2 h1 = __floats2half2_rn(sp[2 * 129], sp[3 * 129]);
        __half2 h2 = __floats2half2_rn(sp[4 * 129], sp[5 * 129]);
        __half2 h3 = __floats2half2_rn(sp[6 * 129], sp[7 * 129]);
        uint4 o;
        o.x = *(unsigned*)&h0; o.y = *(unsigned*)&h1;
        o.z = *(unsigned*)&h2; o.w = *(unsigned*)&h3;
        P4[((size_t)f * TOTAL + (size_t)yy * 512 + xx) * 4 + q] = o;
    }
    // level-1 pool (half scratch)
    for (int i = tid; i < 1024; i += 256) {
        int c = i & 31, to = i >> 5;
        int t00 = 2 * to, t10 = 64 + 2 * to;
        float v = 0.25f * (s[c * 129 + t00] + s[c * 129 + t00 + 1] +
                           s[c * 129 + t10] + s[c * 129 + t10 + 1]);
        SCRATCH[(((size_t)f * 65536 + (size_t)(y0 >> 1) * 256 + (x0 >> 1) + to) * 32) + c] =
            __float2half_rn(v);
    }
}

// ---------------------------------------------------------------------------
// All pools (levels 2..5) directly from level-1 (KxK box average).
// ---------------------------------------------------------------------------
template<int K>
__device__ __forceinline__ void pool_item(int rel, int Rout, int dst) {
    int q = rel & 3;
    int t = rel >> 2;
    int f = t / (Rout * Rout);
    int rem = t - f * Rout * Rout;
    int oy = rem / Rout, ox = rem % Rout;
    const uint4* S4 = (const uint4*)SCRATCH;
    size_t sb = (((size_t)f * 256 + oy * K) * 256 + ox * K) * 4 + q;
    float a[8];
#pragma unroll
    for (int i = 0; i < 8; i++) a[i] = 0.f;
    for (int dy = 0; dy < K; dy++) {
#pragma unroll
        for (int dx = 0; dx < K; dx++) {
            uint4 hv = S4[sb + ((size_t)dy * 256 + dx) * 4];
            const unsigned* p = &hv.x;
#pragma unroll
            for (int j = 0; j < 4; j++) {
                float2 fv = __half22float2(*(const __half2*)&p[j]);
                a[2 * j] += fv.x; a[2 * j + 1] += fv.y;
            }
        }
    }
    float sc = 1.f / (float)(K * K);
    __half2 h0 = __floats2half2_rn(a[0] * sc, a[1] * sc);
    __half2 h1 = __floats2half2_rn(a[2] * sc, a[3] * sc);
    __half2 h2 = __floats2half2_rn(a[4] * sc, a[5] * sc);
    __half2 h3 = __floats2half2_rn(a[6] * sc, a[7] * sc);
    uint4 o;
    o.x = *(unsigned*)&h0; o.y = *(unsigned*)&h1;
    o.z = *(unsigned*)&h2; o.w = *(unsigned*)&h3;
    ((uint4*)SCRATCH)[((size_t)dst + t) * 4 + q] = o;
}

__global__ void k_pool_all() {
    int idx = blockIdx.x * 256 + threadIdx.x;
    if (idx < 6144)        pool_item<16>(idx,          16, 522240);
    else if (idx < 30720)  pool_item<8> (idx - 6144,   32, 516096);
    else if (idx < 129024) pool_item<4> (idx - 30720,  64, 491520);
    else                   pool_item<2> (idx - 129024, 128, 393216);
}

// ---------------------------------------------------------------------------
// Fused GGX filter, all levels, 16x16 tiles (20x20 halo, fp16 smem).
// Thread-group = 2 vertically adjacent texels x one q-slot:
//   - windows share columns, overlap 4/6 rows -> 30 LDS.128/pair (was 50)
//   - vertical pairing keeps 64B lane stride -> conflict-free
// Weights deduped across q-lanes via shfl, pre-normalized; HFMA2 row
// accumulate with fp32 flush per row.
// ---------------------------------------------------------------------------
__global__ void __launch_bounds__(256) k_filter_all() {
    int bid = blockIdx.x;
    int li = 0;
#pragma unroll
    for (int k = 1; k < 5; k++) if (bid >= F_start[k]) li = k;
    int R = 256 >> li;
    int nb = R >> 4;
    int rel = bid - F_start[li];
    int f  = rel / (nb * nb);
    int r2 = rel - f * nb * nb;
    int y0 = (r2 / nb) * 16, x0 = (r2 % nb) * 16;
    size_t inOff   = (size_t)F_inOff[li];
    size_t poolOff = (size_t)F_poolOff[li];
    float a2m1 = F_a2[li] - 1.f;

    __shared__ uint4  hs[20 * 20 * 4];   // 25.6 KB halo data
    __shared__ float4 n3[20 * 20];       // 6.4 KB: (rn, uu*rn, vv*rn, 0)
    int tid = threadIdx.x;
    const uint4* S4 = (const uint4*)SCRATCH;
    float invR2 = 2.0f / (float)R;

    for (int i = tid; i < 1600; i += 256) {
        int t = i >> 2, q = i & 3;
        int hy = t / 20, hx = t - hy * 20;
        int gy = min(max(y0 - 2 + hy, 0), R - 1);
        int gx = min(max(x0 - 2 + hx, 0), R - 1);
        hs[i] = S4[(inOff + ((size_t)f * R + gy) * R + gx) * 4 + q];
    }
    for (int i = tid; i < 400; i += 256) {
        int hy = i / 20, hx = i - hy * 20;
        int gy = min(max(y0 - 2 + hy, 0), R - 1);
        int gx = min(max(x0 - 2 + hx, 0), R - 1);
        float uu = (gx + 0.5f) * invR2 - 1.f;
        float vv = (gy + 0.5f) * invR2 - 1.f;
        float rn = rsqrtf(1.f + uu * uu + vv * vv);
        n3[i] = make_float4(rn, uu * rn, vv * rn, 0.f);
    }
    __syncthreads();

    int q   = tid & 3;
    int grp = tid >> 2;               // 0..63
    uint4* P4 = (uint4*)POOLH;

#pragma unroll
    for (int p = 0; p < 2; p++) {
        int pr = p * 64 + grp;        // pair index 0..127
        int py = pr >> 4;             // 0..7
        int tx = pr & 15;
        int ty0 = py * 2;
        int gy0 = y0 + ty0, gx = x0 + tx;

        float u  = (gx + 0.5f) * invR2 - 1.f;
        float v0 = (gy0 + 0.5f) * invR2 - 1.f;
        float v1 = v0 + invR2;
        float rn00 = rsqrtf(1.f + u * u + v0 * v0);
        float rn01 = rsqrtf(1.f + u * u + v1 * v1);

        // lane q computes weights for taps n = 4k+q, both texels
        float wl0[7], wl1[7];
        float ws0 = 0.f, ws1 = 0.f;
#pragma unroll
        for (int k = 0; k < 7; k++) {
            int n = 4 * k + q;
            float w0 = 0.f, w1 = 0.f;
            if (n < 25) {
                int di = n / 5, dj = n - (n / 5) * 5;
                float4 na = n3[(ty0 + di) * 20 + (tx + dj)];
                float cs0 = fminf((na.x + u * na.y + v0 * na.z) * rn00, 1.f);
                float dn0 = fmaf(cs0 * cs0, a2m1, 1.f);
                w0 = __fdividef(1.f, dn0 * dn0);
                float4 nb = n3[(ty0 + 1 + di) * 20 + (tx + dj)];
                float cs1 = fminf((nb.x + u * nb.y + v1 * nb.z) * rn01, 1.f);
                float dn1 = fmaf(cs1 * cs1, a2m1, 1.f);
                w1 = __fdividef(1.f, dn1 * dn1);
            }
            wl0[k] = w0; wl1[k] = w1;
            ws0 += w0;  ws1 += w1;
        }
        ws0 += __shfl_xor_sync(0xffffffffu, ws0, 1, 4);
        ws0 += __shfl_xor_sync(0xffffffffu, ws0, 2, 4);
        ws1 += __shfl_xor_sync(0xffffffffu, ws1, 1, 4);
        ws1 += __shfl_xor_sync(0xffffffffu, ws1, 2, 4);
        float i0 = __fdividef(1.f, fmaxf(ws0, 1e-8f));
        float i1 = __fdividef(1.f, fmaxf(ws1, 1e-8f));
#pragma unroll
        for (int k = 0; k < 7; k++) { wl0[k] *= i0; wl1[k] *= i1; }

        float f0[8], f1[8];
#pragma unroll
        for (int i = 0; i < 8; i++) { f0[i] = 0.f; f1[i] = 0.f; }

        // 6 halo rows: texel0 uses rows 0..4, texel1 rows 1..5, shared cols
#pragma unroll
        for (int r = 0; r < 6; r++) {
            uint4 d[5];
#pragma unroll
            for (int m = 0; m < 5; m++)
                d[m] = hs[((ty0 + r) * 20 + tx + m) * 4 + q];
            __half2 z = __float2half2_rn(0.f);
            __half2 a0[4] = {z, z, z, z};
            __half2 a1[4] = {z, z, z, z};
#pragma unroll
            for (int m = 0; m < 5; m++) {
                const __half2* pp = (const __half2*)&d[m];
                if (r < 5) {
                    int n = r * 5 + m;
                    float wg = __shfl_sync(0xffffffffu, wl0[n >> 2], n & 3, 4);
                    __half2 wh = __float2half2_rn(wg);
                    a0[0] = __hfma2(wh, pp[0], a0[0]);
                    a0[1] = __hfma2(wh, pp[1], a0[1]);
                    a0[2] = __hfma2(wh, pp[2], a0[2]);
                    a0[3] = __hfma2(wh, pp[3], a0[3]);
                }
                if (r >= 1) {
                    int n = (r - 1) * 5 + m;
                    float wg = __shfl_sync(0xffffffffu, wl1[n >> 2], n & 3, 4);
                    __half2 wh = __float2half2_rn(wg);
                    a1[0] = __hfma2(wh, pp[0], a1[0]);
                    a1[1] = __hfma2(wh, pp[1], a1[1]);
                    a1[2] = __hfma2(wh, pp[2], a1[2]);
                    a1[3] = __hfma2(wh, pp[3], a1[3]);
                }
            }
            if (r < 5) {
#pragma unroll
                for (int j = 0; j < 4; j++) {
                    float2 fv = __half22float2(a0[j]);
                    f0[2 * j] += fv.x; f0[2 * j + 1] += fv.y;
                }
            }
            if (r >= 1) {
#pragma unroll
                for (int j = 0; j < 4; j++) {
                    float2 fv = __half22float2(a1[j]);
                    f1[2 * j] += fv.x; f1[2 * j + 1] += fv.y;
                }
            }
        }

        size_t ob = ((size_t)f * TOTAL + poolOff + (size_t)gy0 * R + gx) * 4 + q;
        {
            __half2 h0 = __floats2half2_rn(f0[0], f0[1]);
            __half2 h1 = __floats2half2_rn(f0[2], f0[3]);
            __half2 h2 = __floats2half2_rn(f0[4], f0[5]);
            __half2 h3 = __floats2half2_rn(f0[6], f0[7]);
            uint4 o;
            o.x = *(unsigned*)&h0; o.y = *(unsigned*)&h1;
            o.z = *(unsigned*)&h2; o.w = *(unsigned*)&h3;
            P4[ob] = o;
        }
        {
            __half2 h0 = __floats2half2_rn(f1[0], f1[1]);
            __half2 h1 = __floats2half2_rn(f1[2], f1[3]);
            __half2 h2 = __floats2half2_rn(f1[4], f1[5]);
            __half2 h3 = __floats2half2_rn(f1[6], f1[7]);
            uint4 o;
            o.x = *(unsigned*)&h0; o.y = *(unsigned*)&h1;
            o.z = *(unsigned*)&h2; o.w = *(unsigned*)&h3;
            P4[ob + (size_t)R * 4] = o;
        }
    }
}

// ---------------------------------------------------------------------------
// Fetch: 4 lanes per query, one uint4 (8 half channels) per lane per tap.
// ---------------------------------------------------------------------------
__global__ void k_fetch(const float* __restrict__ w, const float* __restrict__ rr,
                        float* __restrict__ out, int B) {
    long g = (long)blockIdx.x * 256 + threadIdx.x;
    if (g >= (long)B * 4) return;
    int b = (int)(g >> 2), q = (int)(g & 3);

    float dx = w[b * 3 + 0] * 2.f - 1.f;
    float dy = w[b * 3 + 1] * 2.f - 1.f;
    float dz = w[b * 3 + 2] * 2.f - 1.f;
    float ax = fabsf(dx), ay = fabsf(dy), az = fabsf(dz);
    bool cx = (ax >= ay) && (ax >= az);
    bool cy = (ay >= az) && !cx;
    float ma = cx ? ax : (cy ? ay : az);
    int face = cx ? (dx > 0.f ? 0 : 1) : (cy ? (dy > 0.f ? 2 : 3) : (dz > 0.f ? 4 : 5));
    float un = cx ? (dx > 0.f ? -dz : dz) : (cy ? dx : (dz > 0.f ? dx : -dx));
    float vn = cx ? -dy : (cy ? (dy > 0.f ? dz : -dz) : -dy);
    float inv = 1.f / ma;
    float u01 = (un * inv + 1.f) * 0.5f;
    float v01 = (vn * inv + 1.f) * 0.5f;

    float lev = fminf(fmaxf((rr[b] - 0.03f) * (1.f / 0.96f), 0.f), 1.f) * 5.f;
    int l0 = (int)lev;
    if (l0 > 5) l0 = 5;
    float t = lev - (float)l0;
    int l1 = min(l0 + 1, 5);

    const uint4* P4 = (const uint4*)POOLH;
    size_t fb = (size_t)face * TOTAL;
    float acc[8];
#pragma unroll
    for (int k = 0; k < 8; k++) acc[k] = 0.f;

#pragma unroll
    for (int s = 0; s < 2; s++) {
        int l = s ? l1 : l0;
        float wl = s ? t : (1.f - t);
        int res = 512 >> l;
        float rf = (float)res;
        float x = fminf(fmaxf(u01 * rf - 0.5f, 0.f), rf - 1.f);
        float y = fminf(fmaxf(v01 * rf - 0.5f, 0.f), rf - 1.f);
        int x0 = (int)x, y0 = (int)y;
        int x1 = min(x0 + 1, res - 1), y1 = min(y0 + 1, res - 1);
        float fx = x - (float)x0, fy = y - (float)y0;
        size_t base = fb + d_offs[l];
        size_t r0 = (base + (size_t)y0 * res) * 4 + q;
        size_t r1 = (base + (size_t)y1 * res) * 4 + q;
        uint4 g00 = P4[r0 + (size_t)x0 * 4];
        uint4 g01 = P4[r0 + (size_t)x1 * 4];
        uint4 g10 = P4[r1 + (size_t)x0 * 4];
        uint4 g11 = P4[r1 + (size_t)x1 * 4];
        float w00 = wl * (1.f - fx) * (1.f - fy);
        float w01 = wl * fx * (1.f - fy);
        float w10 = wl * (1.f - fx) * fy;
        float w11 = wl * fx * fy;
        const unsigned* p00 = &g00.x; const unsigned* p01 = &g01.x;
        const unsigned* p10 = &g10.x; const unsigned* p11 = &g11.x;
#pragma unroll
        for (int k = 0; k < 4; k++) {
            float2 f00 = __half22float2(*(const __half2*)&p00[k]);
            float2 f01 = __half22float2(*(const __half2*)&p01[k]);
            float2 f10 = __half22float2(*(const __half2*)&p10[k]);
            float2 f11 = __half22float2(*(const __half2*)&p11[k]);
            acc[2 * k]     += w00 * f00.x + w01 * f01.x + w10 * f10.x + w11 * f11.x;
            acc[2 * k + 1] += w00 * f00.y + w01 * f01.y + w10 * f10.y + w11 * f11.y;
        }
    }
    float4* o4 = (float4*)&out[(size_t)b * 32 + q * 8];
    o4[0] = make_float4(acc[0], acc[1], acc[2], acc[3]);
    o4[1] = make_float4(acc[4], acc[5], acc[6], acc[7]);
}

extern "C" void kernel_launch(void* const* d_in, const int* in_sizes, int n_in,
                              void* d_out, int out_size) {
    const float* feat = (const float*)d_in[0];
    const float* w    = (const float*)d_in[1];
    const float* r    = (const float*)d_in[2];
    float* out = (float*)d_out;
    int B = in_sizes[2];

    k_transpose_pool1<<<dim3(8, 256, 6), 256>>>(feat);
    k_pool_all<<<2040, 256>>>();
    k_filter_all<<<2046, 256>>>();

    long nthreads = (long)B * 4;
    k_fetch<<<(unsigned)((nthreads + 255) / 256), 256>>>(w, r, out, B);
}

// round 10
// speedup vs baseline: 1.3956x; 1.3956x over previous
#include <cuda_runtime.h>
#include <cuda_fp16.h>

#define NC 32
#define NLEV 6
#define TOTAL 349440   // sum of res^2 over 6 levels

// Pool: [face][texel(level-major)][channel], HALF, 134 MB
__device__ __half POOLH[6ll * TOTAL * NC];
// Scratch: unfiltered pooled levels 1..5, channel-last HALF. 33.5 MB
__device__ __half SCRATCH[523776ll * NC];

__constant__ int d_offs[NLEV] = {0, 262144, 327680, 344064, 348160, 349184};

// Fused-filter per-level tables (levels 1..5), 16x16 tiles
__constant__ int   F_start[5]  = {0, 1536, 1920, 2016, 2040};   // total 2046 blocks
__constant__ int   F_inOff[5]  = {0, 393216, 491520, 516096, 522240};
__constant__ int   F_poolOff[5]= {262144, 327680, 344064, 348160, 349184};
__constant__ float F_a2[5]     = {0.00243101246f, 0.030233088f, 0.137822329f, 0.419904f, 0.96059601f}; // rough^4

// ---------------------------------------------------------------------------
// K1: transpose feature (C,6,512,512) -> pool level0 (half, channel-last)
//     AND compute level-1 avg-pool into SCRATCH (half)
// ---------------------------------------------------------------------------
__global__ void k_transpose_pool1(const float* __restrict__ feat) {
    int f = blockIdx.z;
    int x0 = blockIdx.x * 64;
    int y0 = blockIdx.y * 2;
    __shared__ float s[32 * 129];
    int tid = threadIdx.x;

    for (int i = tid; i < 32 * 32; i += 256) {
        int c = i >> 5, v = i & 31;
        int t0 = v * 4;
        int yy = y0 + (t0 >> 6), xx = x0 + (t0 & 63);
        float4 d = *(const float4*)&feat[(((size_t)c * 6 + f) * 512 + yy) * 512 + xx];
        s[c * 129 + t0 + 0] = d.x;
        s[c * 129 + t0 + 1] = d.y;
        s[c * 129 + t0 + 2] = d.z;
        s[c * 129 + t0 + 3] = d.w;
    }
    __syncthreads();

    uint4* P4 = (uint4*)POOLH;   // one uint4 = 8 half channels
    for (int i = tid; i < 512; i += 256) {
        int t = i >> 2, q = i & 3;
        int yy = y0 + (t >> 6), xx = x0 + (t & 63);
        const float* sp = &s[(8 * q) * 129 + t];
        __half2 h0 = __floats2half2_rn(sp[0],       sp[129]);
        __half2 h1 = __floats2half2_rn(sp[2 * 129], sp[3 * 129]);
        __half2 h2 = __floats2half2_rn(sp[4 * 129], sp[5 * 129]);
        __half2 h3 = __floats2half2_rn(sp[6 * 129], sp[7 * 129]);
        uint4 o;
        o.x = *(unsigned*)&h0; o.y = *(unsigned*)&h1;
        o.z = *(unsigned*)&h2; o.w = *(unsigned*)&h3;
        P4[((size_t)f * TOTAL + (size_t)yy * 512 + xx) * 4 + q] = o;
    }
    // level-1 pool (half scratch)
    for (int i = tid; i < 1024; i += 256) {
        int c = i & 31, to = i >> 5;
        int t00 = 2 * to, t10 = 64 + 2 * to;
        float v = 0.25f * (s[c * 129 + t00] + s[c * 129 + t00 + 1] +
                           s[c * 129 + t10] + s[c * 129 + t10 + 1]);
        SCRATCH[(((size_t)f * 65536 + (size_t)(y0 >> 1) * 256 + (x0 >> 1) + to) * 32) + c] =
            __float2half_rn(v);
    }
}

// ---------------------------------------------------------------------------
// All pools (levels 2..5) directly from level-1 (KxK box average).
// ---------------------------------------------------------------------------
template<int K>
__device__ __forceinline__ void pool_item(int rel, int Rout, int dst) {
    int q = rel & 3;
    int t = rel >> 2;
    int f = t / (Rout * Rout);
    int rem = t - f * Rout * Rout;
    int oy = rem / Rout, ox = rem % Rout;
    const uint4* S4 = (const uint4*)SCRATCH;
    size_t sb = (((size_t)f * 256 + oy * K) * 256 + ox * K) * 4 + q;
    float a[8];
#pragma unroll
    for (int i = 0; i < 8; i++) a[i] = 0.f;
    for (int dy = 0; dy < K; dy++) {
#pragma unroll
        for (int dx = 0; dx < K; dx++) {
            uint4 hv = S4[sb + ((size_t)dy * 256 + dx) * 4];
            const unsigned* p = &hv.x;
#pragma unroll
            for (int j = 0; j < 4; j++) {
                float2 fv = __half22float2(*(const __half2*)&p[j]);
                a[2 * j] += fv.x; a[2 * j + 1] += fv.y;
            }
        }
    }
    float sc = 1.f / (float)(K * K);
    __half2 h0 = __floats2half2_rn(a[0] * sc, a[1] * sc);
    __half2 h1 = __floats2half2_rn(a[2] * sc, a[3] * sc);
    __half2 h2 = __floats2half2_rn(a[4] * sc, a[5] * sc);
    __half2 h3 = __floats2half2_rn(a[6] * sc, a[7] * sc);
    uint4 o;
    o.x = *(unsigned*)&h0; o.y = *(unsigned*)&h1;
    o.z = *(unsigned*)&h2; o.w = *(unsigned*)&h3;
    ((uint4*)SCRATCH)[((size_t)dst + t) * 4 + q] = o;
}

__global__ void k_pool_all() {
    int idx = blockIdx.x * 256 + threadIdx.x;
    if (idx < 6144)        pool_item<16>(idx,          16, 522240);
    else if (idx < 30720)  pool_item<8> (idx - 6144,   32, 516096);
    else if (idx < 129024) pool_item<4> (idx - 30720,  64, 491520);
    else                   pool_item<2> (idx - 129024, 128, 393216);
}

// ---------------------------------------------------------------------------
// Fused GGX filter, all levels, 16x16 tiles (20x20 halo, fp16 smem).
// Thread-group = 2 vertically adjacent texels x one q-slot:
//   30 LDS.128/pair (was 50); 64B lane stride stays conflict-free.
// Halo uint4 is consumed immediately (no d[5] buffer) -> low reg pressure.
// ---------------------------------------------------------------------------
__global__ void __launch_bounds__(256) k_filter_all() {
    int bid = blockIdx.x;
    int li = 0;
#pragma unroll
    for (int k = 1; k < 5; k++) if (bid >= F_start[k]) li = k;
    int R = 256 >> li;
    int nb = R >> 4;
    int rel = bid - F_start[li];
    int f  = rel / (nb * nb);
    int r2 = rel - f * nb * nb;
    int y0 = (r2 / nb) * 16, x0 = (r2 % nb) * 16;
    size_t inOff   = (size_t)F_inOff[li];
    size_t poolOff = (size_t)F_poolOff[li];
    float a2m1 = F_a2[li] - 1.f;

    __shared__ uint4  hs[20 * 20 * 4];   // 25.6 KB halo data
    __shared__ float4 n3[20 * 20];       // 6.4 KB: (rn, uu*rn, vv*rn, 0)
    int tid = threadIdx.x;
    const uint4* S4 = (const uint4*)SCRATCH;
    float invR2 = 2.0f / (float)R;

    for (int i = tid; i < 1600; i += 256) {
        int t = i >> 2, q = i & 3;
        int hy = t / 20, hx = t - hy * 20;
        int gy = min(max(y0 - 2 + hy, 0), R - 1);
        int gx = min(max(x0 - 2 + hx, 0), R - 1);
        hs[i] = S4[(inOff + ((size_t)f * R + gy) * R + gx) * 4 + q];
    }
    for (int i = tid; i < 400; i += 256) {
        int hy = i / 20, hx = i - hy * 20;
        int gy = min(max(y0 - 2 + hy, 0), R - 1);
        int gx = min(max(x0 - 2 + hx, 0), R - 1);
        float uu = (gx + 0.5f) * invR2 - 1.f;
        float vv = (gy + 0.5f) * invR2 - 1.f;
        float rn = rsqrtf(1.f + uu * uu + vv * vv);
        n3[i] = make_float4(rn, uu * rn, vv * rn, 0.f);
    }
    __syncthreads();

    int q   = tid & 3;
    int grp = tid >> 2;               // 0..63
    uint4* P4 = (uint4*)POOLH;

#pragma unroll
    for (int p = 0; p < 2; p++) {
        int pr = p * 64 + grp;        // pair index 0..127
        int py = pr >> 4;             // 0..7
        int tx = pr & 15;
        int ty0 = py * 2;
        int gy0 = y0 + ty0, gx = x0 + tx;

        float u  = (gx + 0.5f) * invR2 - 1.f;
        float v0 = (gy0 + 0.5f) * invR2 - 1.f;
        float v1 = v0 + invR2;
        float rn00 = rsqrtf(1.f + u * u + v0 * v0);
        float rn01 = rsqrtf(1.f + u * u + v1 * v1);

        // lane q computes weights for taps n = 4k+q, both texels
        float wl0[7], wl1[7];
        float ws0 = 0.f, ws1 = 0.f;
#pragma unroll
        for (int k = 0; k < 7; k++) {
            int n = 4 * k + q;
            float w0 = 0.f, w1 = 0.f;
            if (n < 25) {
                int di = n / 5, dj = n - (n / 5) * 5;
                float4 na = n3[(ty0 + di) * 20 + (tx + dj)];
                float cs0 = fminf((na.x + u * na.y + v0 * na.z) * rn00, 1.f);
                float dn0 = fmaf(cs0 * cs0, a2m1, 1.f);
                w0 = __fdividef(1.f, dn0 * dn0);
                float4 nb = n3[(ty0 + 1 + di) * 20 + (tx + dj)];
                float cs1 = fminf((nb.x + u * nb.y + v1 * nb.z) * rn01, 1.f);
                float dn1 = fmaf(cs1 * cs1, a2m1, 1.f);
                w1 = __fdividef(1.f, dn1 * dn1);
            }
            wl0[k] = w0; wl1[k] = w1;
            ws0 += w0;  ws1 += w1;
        }
        ws0 += __shfl_xor_sync(0xffffffffu, ws0, 1, 4);
        ws0 += __shfl_xor_sync(0xffffffffu, ws0, 2, 4);
        ws1 += __shfl_xor_sync(0xffffffffu, ws1, 1, 4);
        ws1 += __shfl_xor_sync(0xffffffffu, ws1, 2, 4);
        float i0 = __fdividef(1.f, fmaxf(ws0, 1e-8f));
        float i1 = __fdividef(1.f, fmaxf(ws1, 1e-8f));
#pragma unroll
        for (int k = 0; k < 7; k++) { wl0[k] *= i0; wl1[k] *= i1; }

        float f0[8], f1[8];
#pragma unroll
        for (int i = 0; i < 8; i++) { f0[i] = 0.f; f1[i] = 0.f; }

        // 6 halo rows: texel0 uses rows 0..4, texel1 rows 1..5, shared cols.
        // Each uint4 is read once and consumed immediately by both texels.
#pragma unroll
        for (int r = 0; r < 6; r++) {
            __half2 z = __float2half2_rn(0.f);
            __half2 a0[4] = {z, z, z, z};
            __half2 a1[4] = {z, z, z, z};
#pragma unroll
            for (int m = 0; m < 5; m++) {
                uint4 hv = hs[((ty0 + r) * 20 + tx + m) * 4 + q];
                const __half2* pp = (const __half2*)&hv;
                if (r < 5) {
                    int n = r * 5 + m;
                    float wg = __shfl_sync(0xffffffffu, wl0[n >> 2], n & 3, 4);
                    __half2 wh = __float2half2_rn(wg);
                    a0[0] = __hfma2(wh, pp[0], a0[0]);
                    a0[1] = __hfma2(wh, pp[1], a0[1]);
                    a0[2] = __hfma2(wh, pp[2], a0[2]);
                    a0[3] = __hfma2(wh, pp[3], a0[3]);
                }
                if (r >= 1) {
                    int n = (r - 1) * 5 + m;
                    float wg = __shfl_sync(0xffffffffu, wl1[n >> 2], n & 3, 4);
                    __half2 wh = __float2half2_rn(wg);
                    a1[0] = __hfma2(wh, pp[0], a1[0]);
                    a1[1] = __hfma2(wh, pp[1], a1[1]);
                    a1[2] = __hfma2(wh, pp[2], a1[2]);
                    a1[3] = __hfma2(wh, pp[3], a1[3]);
                }
            }
            if (r < 5) {
#pragma unroll
                for (int j = 0; j < 4; j++) {
                    float2 fv = __half22float2(a0[j]);
                    f0[2 * j] += fv.x; f0[2 * j + 1] += fv.y;
                }
            }
            if (r >= 1) {
#pragma unroll
                for (int j = 0; j < 4; j++) {
                    float2 fv = __half22float2(a1[j]);
                    f1[2 * j] += fv.x; f1[2 * j + 1] += fv.y;
                }
            }
        }

        size_t ob = ((size_t)f * TOTAL + poolOff + (size_t)gy0 * R + gx) * 4 + q;
        {
            __half2 h0 = __floats2half2_rn(f0[0], f0[1]);
            __half2 h1 = __floats2half2_rn(f0[2], f0[3]);
            __half2 h2 = __floats2half2_rn(f0[4], f0[5]);
            __half2 h3 = __floats2half2_rn(f0[6], f0[7]);
            uint4 o;
            o.x = *(unsigned*)&h0; o.y = *(unsigned*)&h1;
            o.z = *(unsigned*)&h2; o.w = *(unsigned*)&h3;
            P4[ob] = o;
        }
        {
            __half2 h0 = __floats2half2_rn(f1[0], f1[1]);
            __half2 h1 = __floats2half2_rn(f1[2], f1[3]);
            __half2 h2 = __floats2half2_rn(f1[4], f1[5]);
            __half2 h3 = __floats2half2_rn(f1[6], f1[7]);
            uint4 o;
            o.x = *(unsigned*)&h0; o.y = *(unsigned*)&h1;
            o.z = *(unsigned*)&h2; o.w = *(unsigned*)&h3;
            P4[ob + (size_t)R * 4] = o;
        }
    }
}

// ---------------------------------------------------------------------------
// Fetch: 4 lanes per query, one uint4 (8 half channels) per lane per tap.
// ---------------------------------------------------------------------------
__global__ void k_fetch(const float* __restrict__ w, const float* __restrict__ rr,
                        float* __restrict__ out, int B) {
    long g = (long)blockIdx.x * 256 + threadIdx.x;
    if (g >= (long)B * 4) return;
    int b = (int)(g >> 2), q = (int)(g & 3);

    float dx = w[b * 3 + 0] * 2.f - 1.f;
    float dy = w[b * 3 + 1] * 2.f - 1.f;
    float dz = w[b * 3 + 2] * 2.f - 1.f;
    float ax = fabsf(dx), ay = fabsf(dy), az = fabsf(dz);
    bool cx = (ax >= ay) && (ax >= az);
    bool cy = (ay >= az) && !cx;
    float ma = cx ? ax : (cy ? ay : az);
    int face = cx ? (dx > 0.f ? 0 : 1) : (cy ? (dy > 0.f ? 2 : 3) : (dz > 0.f ? 4 : 5));
    float un = cx ? (dx > 0.f ? -dz : dz) : (cy ? dx : (dz > 0.f ? dx : -dx));
    float vn = cx ? -dy : (cy ? (dy > 0.f ? dz : -dz) : -dy);
    float inv = 1.f / ma;
    float u01 = (un * inv + 1.f) * 0.5f;
    float v01 = (vn * inv + 1.f) * 0.5f;

    float lev = fminf(fmaxf((rr[b] - 0.03f) * (1.f / 0.96f), 0.f), 1.f) * 5.f;
    int l0 = (int)lev;
    if (l0 > 5) l0 = 5;
    float t = lev - (float)l0;
    int l1 = min(l0 + 1, 5);

    const uint4* P4 = (const uint4*)POOLH;
    size_t fb = (size_t)face * TOTAL;
    float acc[8];
#pragma unroll
    for (int k = 0; k < 8; k++) acc[k] = 0.f;

#pragma unroll
    for (int s = 0; s < 2; s++) {
        int l = s ? l1 : l0;
        float wl = s ? t : (1.f - t);
        int res = 512 >> l;
        float rf = (float)res;
        float x = fminf(fmaxf(u01 * rf - 0.5f, 0.f), rf - 1.f);
        float y = fminf(fmaxf(v01 * rf - 0.5f, 0.f), rf - 1.f);
        int x0 = (int)x, y0 = (int)y;
        int x1 = min(x0 + 1, res - 1), y1 = min(y0 + 1, res - 1);
        float fx = x - (float)x0, fy = y - (float)y0;
        size_t base = fb + d_offs[l];
        size_t r0 = (base + (size_t)y0 * res) * 4 + q;
        size_t r1 = (base + (size_t)y1 * res) * 4 + q;
        uint4 g00 = P4[r0 + (size_t)x0 * 4];
        uint4 g01 = P4[r0 + (size_t)x1 * 4];
        uint4 g10 = P4[r1 + (size_t)x0 * 4];
        uint4 g11 = P4[r1 + (size_t)x1 * 4];
        float w00 = wl * (1.f - fx) * (1.f - fy);
        float w01 = wl * fx * (1.f - fy);
        float w10 = wl * (1.f - fx) * fy;
        float w11 = wl * fx * fy;
        const unsigned* p00 = &g00.x; const unsigned* p01 = &g01.x;
        const unsigned* p10 = &g10.x; const unsigned* p11 = &g11.x;
#pragma unroll
        for (int k = 0; k < 4; k++) {
            float2 f00 = __half22float2(*(const __half2*)&p00[k]);
            float2 f01 = __half22float2(*(const __half2*)&p01[k]);
            float2 f10 = __half22float2(*(const __half2*)&p10[k]);
            float2 f11 = __half22float2(*(const __half2*)&p11[k]);
            acc[2 * k]     += w00 * f00.x + w01 * f01.x + w10 * f10.x + w11 * f11.x;
            acc[2 * k + 1] += w00 * f00.y + w01 * f01.y + w10 * f10.y + w11 * f11.y;
        }
    }
    float4* o4 = (float4*)&out[(size_t)b * 32 + q * 8];
    o4[0] = make_float4(acc[0], acc[1], acc[2], acc[3]);
    o4[1] = make_float4(acc[4], acc[5], acc[6], acc[7]);
}

extern "C" void kernel_launch(void* const* d_in, const int* in_sizes, int n_in,
                              void* d_out, int out_size) {
    const float* feat = (const float*)d_in[0];
    const float* w    = (const float*)d_in[1];
    const float* r    = (const float*)d_in[2];
    float* out = (float*)d_out;
    int B = in_sizes[2];

    k_transpose_pool1<<<dim3(8, 256, 6), 256>>>(feat);
    k_pool_all<<<2040, 256>>>();
    k_filter_all<<<2046, 256>>>();

    long nthreads = (long)B * 4;
    k_fetch<<<(unsigned)((nthreads + 255) / 256), 256>>>(w, r, out, B);
}

// round 11
// speedup vs baseline: 1.4313x; 1.0256x over previous
#include <cuda_runtime.h>
#include <cuda_fp16.h>

#define NC 32
#define NLEV 6
#define TOTAL 349440   // sum of res^2 over 6 levels

// Pool: [face][texel(level-major)][channel], HALF, 134 MB
__device__ __half POOLH[6ll * TOTAL * NC];
// Scratch: unfiltered pooled levels 1..5, channel-last HALF. 33.5 MB
__device__ __half SCRATCH[523776ll * NC];

__constant__ int d_offs[NLEV] = {0, 262144, 327680, 344064, 348160, 349184};

// Fused-filter per-level tables (levels 1..5), 16x16 tiles
__constant__ int   F_start[5]  = {0, 1536, 1920, 2016, 2040};   // total 2046 blocks
__constant__ int   F_inOff[5]  = {0, 393216, 491520, 516096, 522240};
__constant__ int   F_poolOff[5]= {262144, 327680, 344064, 348160, 349184};
__constant__ float F_a2[5]     = {0.00243101246f, 0.030233088f, 0.137822329f, 0.419904f, 0.96059601f}; // rough^4

// ---------------------------------------------------------------------------
// K1: transpose feature (C,6,512,512) -> pool level0 (half, channel-last)
//     AND compute level-1 avg-pool into SCRATCH (half)
// ---------------------------------------------------------------------------
__global__ void k_transpose_pool1(const float* __restrict__ feat) {
    int f = blockIdx.z;
    int x0 = blockIdx.x * 64;
    int y0 = blockIdx.y * 2;
    __shared__ float s[32 * 129];
    int tid = threadIdx.x;

    for (int i = tid; i < 32 * 32; i += 256) {
        int c = i >> 5, v = i & 31;
        int t0 = v * 4;
        int yy = y0 + (t0 >> 6), xx = x0 + (t0 & 63);
        float4 d = *(const float4*)&feat[(((size_t)c * 6 + f) * 512 + yy) * 512 + xx];
        s[c * 129 + t0 + 0] = d.x;
        s[c * 129 + t0 + 1] = d.y;
        s[c * 129 + t0 + 2] = d.z;
        s[c * 129 + t0 + 3] = d.w;
    }
    __syncthreads();

    uint4* P4 = (uint4*)POOLH;   // one uint4 = 8 half channels
    for (int i = tid; i < 512; i += 256) {
        int t = i >> 2, q = i & 3;
        int yy = y0 + (t >> 6), xx = x0 + (t & 63);
        const float* sp = &s[(8 * q) * 129 + t];
        __half2 h0 = __floats2half2_rn(sp[0],       sp[129]);
        __half2 h1 = __floats2half2_rn(sp[2 * 129], sp[3 * 129]);
        __half2 h2 = __floats2half2_rn(sp[4 * 129], sp[5 * 129]);
        __half2 h3 = __floats2half2_rn(sp[6 * 129], sp[7 * 129]);
        uint4 o;
        o.x = *(unsigned*)&h0; o.y = *(unsigned*)&h1;
        o.z = *(unsigned*)&h2; o.w = *(unsigned*)&h3;
        P4[((size_t)f * TOTAL + (size_t)yy * 512 + xx) * 4 + q] = o;
    }
    // level-1 pool (half scratch)
    for (int i = tid; i < 1024; i += 256) {
        int c = i & 31, to = i >> 5;
        int t00 = 2 * to, t10 = 64 + 2 * to;
        float v = 0.25f * (s[c * 129 + t00] + s[c * 129 + t00 + 1] +
                           s[c * 129 + t10] + s[c * 129 + t10 + 1]);
        SCRATCH[(((size_t)f * 65536 + (size_t)(y0 >> 1) * 256 + (x0 >> 1) + to) * 32) + c] =
            __float2half_rn(v);
    }
}

// ---------------------------------------------------------------------------
// All pools (levels 2..5) directly from level-1 (KxK box average).
// ---------------------------------------------------------------------------
template<int K>
__device__ __forceinline__ void pool_item(int rel, int Rout, int dst) {
    int q = rel & 3;
    int t = rel >> 2;
    int f = t / (Rout * Rout);
    int rem = t - f * Rout * Rout;
    int oy = rem / Rout, ox = rem % Rout;
    const uint4* S4 = (const uint4*)SCRATCH;
    size_t sb = (((size_t)f * 256 + oy * K) * 256 + ox * K) * 4 + q;
    float a[8];
#pragma unroll
    for (int i = 0; i < 8; i++) a[i] = 0.f;
    for (int dy = 0; dy < K; dy++) {
#pragma unroll
        for (int dx = 0; dx < K; dx++) {
            uint4 hv = S4[sb + ((size_t)dy * 256 + dx) * 4];
            const unsigned* p = &hv.x;
#pragma unroll
            for (int j = 0; j < 4; j++) {
                float2 fv = __half22float2(*(const __half2*)&p[j]);
                a[2 * j] += fv.x; a[2 * j + 1] += fv.y;
            }
        }
    }
    float sc = 1.f / (float)(K * K);
    __half2 h0 = __floats2half2_rn(a[0] * sc, a[1] * sc);
    __half2 h1 = __floats2half2_rn(a[2] * sc, a[3] * sc);
    __half2 h2 = __floats2half2_rn(a[4] * sc, a[5] * sc);
    __half2 h3 = __floats2half2_rn(a[6] * sc, a[7] * sc);
    uint4 o;
    o.x = *(unsigned*)&h0; o.y = *(unsigned*)&h1;
    o.z = *(unsigned*)&h2; o.w = *(unsigned*)&h3;
    ((uint4*)SCRATCH)[((size_t)dst + t) * 4 + q] = o;
}

__global__ void k_pool_all() {
    int idx = blockIdx.x * 256 + threadIdx.x;
    if (idx < 6144)        pool_item<16>(idx,          16, 522240);
    else if (idx < 30720)  pool_item<8> (idx - 6144,   32, 516096);
    else if (idx < 129024) pool_item<4> (idx - 30720,  64, 491520);
    else                   pool_item<2> (idx - 129024, 128, 393216);
}

// ---------------------------------------------------------------------------
// Fused GGX filter, all levels, 16x16 tiles (20x20 halo, fp16 smem).
// Thread-group = 2 vertically adjacent texels x one q-slot.
// Weight ownership is by PHYSICAL halo tap np=0..29 (np&3 -> lane): the pack
// (wl0[np], wl1[np-5]) weights the SAME physical texel, so each tap needs ONE
// n3 read and ONE shfl (30/pair, was 50). Weights fp16-quantized, wsum from
// the quantized values (normalization divides the quantization out exactly).
// ---------------------------------------------------------------------------
__global__ void __launch_bounds__(256) k_filter_all() {
    int bid = blockIdx.x;
    int li = 0;
#pragma unroll
    for (int k = 1; k < 5; k++) if (bid >= F_start[k]) li = k;
    int R = 256 >> li;
    int nb = R >> 4;
    int rel = bid - F_start[li];
    int f  = rel / (nb * nb);
    int r2 = rel - f * nb * nb;
    int y0 = (r2 / nb) * 16, x0 = (r2 % nb) * 16;
    size_t inOff   = (size_t)F_inOff[li];
    size_t poolOff = (size_t)F_poolOff[li];
    float a2   = F_a2[li];
    float a2m1 = a2 - 1.f;

    __shared__ uint4  hs[20 * 20 * 4];   // 25.6 KB halo data
    __shared__ float4 n3[20 * 20];       // 6.4 KB: (rn, uu*rn, vv*rn, 0)
    int tid = threadIdx.x;
    const uint4* S4 = (const uint4*)SCRATCH;
    float invR2 = 2.0f / (float)R;

    for (int i = tid; i < 1600; i += 256) {
        int t = i >> 2, q = i & 3;
        int hy = t / 20, hx = t - hy * 20;
        int gy = min(max(y0 - 2 + hy, 0), R - 1);
        int gx = min(max(x0 - 2 + hx, 0), R - 1);
        hs[i] = S4[(inOff + ((size_t)f * R + gy) * R + gx) * 4 + q];
    }
    for (int i = tid; i < 400; i += 256) {
        int hy = i / 20, hx = i - hy * 20;
        int gy = min(max(y0 - 2 + hy, 0), R - 1);
        int gx = min(max(x0 - 2 + hx, 0), R - 1);
        float uu = (gx + 0.5f) * invR2 - 1.f;
        float vv = (gy + 0.5f) * invR2 - 1.f;
        float rn = rsqrtf(1.f + uu * uu + vv * vv);
        n3[i] = make_float4(rn, uu * rn, vv * rn, 0.f);
    }
    __syncthreads();

    int q   = tid & 3;
    int grp = tid >> 2;               // 0..63
    uint4* P4 = (uint4*)POOLH;

#pragma unroll
    for (int p = 0; p < 2; p++) {
        int pr = p * 64 + grp;        // pair index 0..127
        int py = pr >> 4;             // 0..7
        int tx = pr & 15;
        int ty0 = py * 2;
        int gy0 = y0 + ty0, gx = x0 + tx;

        float u  = (gx + 0.5f) * invR2 - 1.f;
        float v0 = (gy0 + 0.5f) * invR2 - 1.f;
        float v1 = v0 + invR2;
        float rn00 = rsqrtf(1.f + u * u + v0 * v0);
        float rn01 = rsqrtf(1.f + u * u + v1 * v1);

        // lane q owns physical taps np = 4k+q (np<30). Pack per tap:
        //   lo = texel0 weight (tap np, valid np<25)
        //   hi = texel1 weight (tap np-5, valid np>=5)
        unsigned pk[8];
        float ws0 = 0.f, ws1 = 0.f;
#pragma unroll
        for (int k = 0; k < 8; k++) {
            int np = 4 * k + q;
            float w0 = 0.f, w1 = 0.f;
            if (np < 30) {
                int rp = np / 5, cp = np - rp * 5;
                float4 nn = n3[(ty0 + rp) * 20 + (tx + cp)];
                float base = nn.x + u * nn.y;
                if (np < 25) {
                    float cs = fminf(fmaf(v0, nn.z, base) * rn00, 1.f);
                    float dn = fmaf(cs * cs, a2m1, 1.f);
                    w0 = __fdividef(a2, dn * dn);
                }
                if (np >= 5) {
                    float cs = fminf(fmaf(v1, nn.z, base) * rn01, 1.f);
                    float dn = fmaf(cs * cs, a2m1, 1.f);
                    w1 = __fdividef(a2, dn * dn);
                }
            }
            __half2 hp = __floats2half2_rn(w0, w1);
            pk[k] = *(unsigned*)&hp;
            float2 bq = __half22float2(hp);
            ws0 += bq.x; ws1 += bq.y;
        }
        ws0 += __shfl_xor_sync(0xffffffffu, ws0, 1, 4);
        ws0 += __shfl_xor_sync(0xffffffffu, ws0, 2, 4);
        ws1 += __shfl_xor_sync(0xffffffffu, ws1, 1, 4);
        ws1 += __shfl_xor_sync(0xffffffffu, ws1, 2, 4);
        float i0 = __fdividef(1.f, fmaxf(ws0, 1e-8f));
        float i1 = __fdividef(1.f, fmaxf(ws1, 1e-8f));

        float f0[8], f1[8];
#pragma unroll
        for (int i = 0; i < 8; i++) { f0[i] = 0.f; f1[i] = 0.f; }

        // 6 halo rows; one shfl + one data-LDS per physical tap serves both texels
#pragma unroll
        for (int r = 0; r < 6; r++) {
            __half2 z = __float2half2_rn(0.f);
            __half2 a0[4] = {z, z, z, z};
            __half2 a1[4] = {z, z, z, z};
#pragma unroll
            for (int m = 0; m < 5; m++) {
                int np = r * 5 + m;
                unsigned wg = __shfl_sync(0xffffffffu, pk[np >> 2], np & 3, 4);
                __half2 wp = *(__half2*)&wg;
                uint4 hv = hs[((ty0 + r) * 20 + tx + m) * 4 + q];
                const __half2* pp = (const __half2*)&hv;
                if (r < 5) {
                    __half2 wh0 = __half2half2(__low2half(wp));
                    a0[0] = __hfma2(wh0, pp[0], a0[0]);
                    a0[1] = __hfma2(wh0, pp[1], a0[1]);
                    a0[2] = __hfma2(wh0, pp[2], a0[2]);
                    a0[3] = __hfma2(wh0, pp[3], a0[3]);
                }
                if (r >= 1) {
                    __half2 wh1 = __half2half2(__high2half(wp));
                    a1[0] = __hfma2(wh1, pp[0], a1[0]);
                    a1[1] = __hfma2(wh1, pp[1], a1[1]);
                    a1[2] = __hfma2(wh1, pp[2], a1[2]);
                    a1[3] = __hfma2(wh1, pp[3], a1[3]);
                }
            }
            if (r < 5) {
#pragma unroll
                for (int j = 0; j < 4; j++) {
                    float2 fv = __half22float2(a0[j]);
                    f0[2 * j] += fv.x; f0[2 * j + 1] += fv.y;
                }
            }
            if (r >= 1) {
#pragma unroll
                for (int j = 0; j < 4; j++) {
                    float2 fv = __half22float2(a1[j]);
                    f1[2 * j] += fv.x; f1[2 * j + 1] += fv.y;
                }
            }
        }

        size_t ob = ((size_t)f * TOTAL + poolOff + (size_t)gy0 * R + gx) * 4 + q;
        {
            __half2 h0 = __floats2half2_rn(f0[0] * i0, f0[1] * i0);
            __half2 h1 = __floats2half2_rn(f0[2] * i0, f0[3] * i0);
            __half2 h2 = __floats2half2_rn(f0[4] * i0, f0[5] * i0);
            __half2 h3 = __floats2half2_rn(f0[6] * i0, f0[7] * i0);
            uint4 o;
            o.x = *(unsigned*)&h0; o.y = *(unsigned*)&h1;
            o.z = *(unsigned*)&h2; o.w = *(unsigned*)&h3;
            P4[ob] = o;
        }
        {
            __half2 h0 = __floats2half2_rn(f1[0] * i1, f1[1] * i1);
            __half2 h1 = __floats2half2_rn(f1[2] * i1, f1[3] * i1);
            __half2 h2 = __floats2half2_rn(f1[4] * i1, f1[5] * i1);
            __half2 h3 = __floats2half2_rn(f1[6] * i1, f1[7] * i1);
            uint4 o;
            o.x = *(unsigned*)&h0; o.y = *(unsigned*)&h1;
            o.z = *(unsigned*)&h2; o.w = *(unsigned*)&h3;
            P4[ob + (size_t)R * 4] = o;
        }
    }
}

// ---------------------------------------------------------------------------
// Fetch: 4 lanes per query, one uint4 (8 half channels) per lane per tap.
// ---------------------------------------------------------------------------
__global__ void k_fetch(const float* __restrict__ w, const float* __restrict__ rr,
                        float* __restrict__ out, int B) {
    long g = (long)blockIdx.x * 256 + threadIdx.x;
    if (g >= (long)B * 4) return;
    int b = (int)(g >> 2), q = (int)(g & 3);

    float dx = w[b * 3 + 0] * 2.f - 1.f;
    float dy = w[b * 3 + 1] * 2.f - 1.f;
    float dz = w[b * 3 + 2] * 2.f - 1.f;
    float ax = fabsf(dx), ay = fabsf(dy), az = fabsf(dz);
    bool cx = (ax >= ay) && (ax >= az);
    bool cy = (ay >= az) && !cx;
    float ma = cx ? ax : (cy ? ay : az);
    int face = cx ? (dx > 0.f ? 0 : 1) : (cy ? (dy > 0.f ? 2 : 3) : (dz > 0.f ? 4 : 5));
    float un = cx ? (dx > 0.f ? -dz : dz) : (cy ? dx : (dz > 0.f ? dx : -dx));
    float vn = cx ? -dy : (cy ? (dy > 0.f ? dz : -dz) : -dy);
    float inv = 1.f / ma;
    float u01 = (un * inv + 1.f) * 0.5f;
    float v01 = (vn * inv + 1.f) * 0.5f;

    float lev = fminf(fmaxf((rr[b] - 0.03f) * (1.f / 0.96f), 0.f), 1.f) * 5.f;
    int l0 = (int)lev;
    if (l0 > 5) l0 = 5;
    float t = lev - (float)l0;
    int l1 = min(l0 + 1, 5);

    const uint4* P4 = (const uint4*)POOLH;
    size_t fb = (size_t)face * TOTAL;
    float acc[8];
#pragma unroll
    for (int k = 0; k < 8; k++) acc[k] = 0.f;

#pragma unroll
    for (int s = 0; s < 2; s++) {
        int l = s ? l1 : l0;
        float wl = s ? t : (1.f - t);
        int res = 512 >> l;
        float rf = (float)res;
        float x = fminf(fmaxf(u01 * rf - 0.5f, 0.f), rf - 1.f);
        float y = fminf(fmaxf(v01 * rf - 0.5f, 0.f), rf - 1.f);
        int x0 = (int)x, y0 = (int)y;
        int x1 = min(x0 + 1, res - 1), y1 = min(y0 + 1, res - 1);
        float fx = x - (float)x0, fy = y - (float)y0;
        size_t base = fb + d_offs[l];
        size_t r0 = (base + (size_t)y0 * res) * 4 + q;
        size_t r1 = (base + (size_t)y1 * res) * 4 + q;
        uint4 g00 = P4[r0 + (size_t)x0 * 4];
        uint4 g01 = P4[r0 + (size_t)x1 * 4];
        uint4 g10 = P4[r1 + (size_t)x0 * 4];
        uint4 g11 = P4[r1 + (size_t)x1 * 4];
        float w00 = wl * (1.f - fx) * (1.f - fy);
        float w01 = wl * fx * (1.f - fy);
        float w10 = wl * (1.f - fx) * fy;
        float w11 = wl * fx * fy;
        const unsigned* p00 = &g00.x; const unsigned* p01 = &g01.x;
        const unsigned* p10 = &g10.x; const unsigned* p11 = &g11.x;
#pragma unroll
        for (int k = 0; k < 4; k++) {
            float2 f00 = __half22float2(*(const __half2*)&p00[k]);
            float2 f01 = __half22float2(*(const __half2*)&p01[k]);
            float2 f10 = __half22float2(*(const __half2*)&p10[k]);
            float2 f11 = __half22float2(*(const __half2*)&p11[k]);
            acc[2 * k]     += w00 * f00.x + w01 * f01.x + w10 * f10.x + w11 * f11.x;
            acc[2 * k + 1] += w00 * f00.y + w01 * f01.y + w10 * f10.y + w11 * f11.y;
        }
    }
    float4* o4 = (float4*)&out[(size_t)b * 32 + q * 8];
    o4[0] = make_float4(acc[0], acc[1], acc[2], acc[3]);
    o4[1] = make_float4(acc[4], acc[5], acc[6], acc[7]);
}

extern "C" void kernel_launch(void* const* d_in, const int* in_sizes, int n_in,
                              void* d_out, int out_size) {
    const float* feat = (const float*)d_in[0];
    const float* w    = (const float*)d_in[1];
    const float* r    = (const float*)d_in[2];
    float* out = (float*)d_out;
    int B = in_sizes[2];

    k_transpose_pool1<<<dim3(8, 256, 6), 256>>>(feat);
    k_pool_all<<<2040, 256>>>();
    k_filter_all<<<2046, 256>>>();

    long nthreads = (long)B * 4;
    k_fetch<<<(unsigned)((nthreads + 255) / 256), 256>>>(w, r, out, B);
}

// round 14
// speedup vs baseline: 1.6141x; 1.1277x over previous
#include <cuda_runtime.h>
#include <cuda_fp16.h>

#define NC 32
#define NLEV 6
#define TOTAL 349440   // sum of res^2 over 6 levels

// Pool: [face][texel(level-major)][channel], HALF, 134 MB
__device__ __half POOLH[6ll * TOTAL * NC];
// Scratch: unfiltered pooled levels 1..5, channel-last HALF. 33.5 MB
__device__ __half SCRATCH[523776ll * NC];

__constant__ int d_offs[NLEV] = {0, 262144, 327680, 344064, 348160, 349184};

// Per-level filter tables (levels 1..5)
__constant__ int   F_inOff[6]  = {0, 0, 393216, 491520, 516096, 522240};   // index by level
__constant__ int   F_poolOff[6]= {0, 262144, 327680, 344064, 348160, 349184};
__constant__ float F_a2[6]     = {0.f, 0.00243101246f, 0.030233088f, 0.137822329f, 0.419904f, 0.96059601f}; // rough^4

// ---------------------------------------------------------------------------
// K1: transpose feature (C,6,512,512) -> pool level0 (half, channel-last)
//     AND compute level-1 avg-pool into SCRATCH (half, vectorized store)
// ---------------------------------------------------------------------------
__global__ void k_transpose_pool1(const float* __restrict__ feat) {
    int f = blockIdx.z;
    int x0 = blockIdx.x * 64;
    int y0 = blockIdx.y * 2;
    __shared__ float s[32 * 129];
    int tid = threadIdx.x;

    for (int i = tid; i < 32 * 32; i += 256) {
        int c = i >> 5, v = i & 31;
        int t0 = v * 4;
        int yy = y0 + (t0 >> 6), xx = x0 + (t0 & 63);
        float4 d = *(const float4*)&feat[(((size_t)c * 6 + f) * 512 + yy) * 512 + xx];
        s[c * 129 + t0 + 0] = d.x;
        s[c * 129 + t0 + 1] = d.y;
        s[c * 129 + t0 + 2] = d.z;
        s[c * 129 + t0 + 3] = d.w;
    }
    __syncthreads();

    uint4* P4 = (uint4*)POOLH;   // one uint4 = 8 half channels
    for (int i = tid; i < 512; i += 256) {
        int t = i >> 2, q = i & 3;
        int yy = y0 + (t >> 6), xx = x0 + (t & 63);
        const float* sp = &s[(8 * q) * 129 + t];
        __half2 h0 = __floats2half2_rn(sp[0],       sp[129]);
        __half2 h1 = __floats2half2_rn(sp[2 * 129], sp[3 * 129]);
        __half2 h2 = __floats2half2_rn(sp[4 * 129], sp[5 * 129]);
        __half2 h3 = __floats2half2_rn(sp[6 * 129], sp[7 * 129]);
        uint4 o;
        o.x = *(unsigned*)&h0; o.y = *(unsigned*)&h1;
        o.z = *(unsigned*)&h2; o.w = *(unsigned*)&h3;
        P4[((unsigned)f * TOTAL + (unsigned)yy * 512 + xx) * 4 + q] = o;
    }
    // level-1 pool: 32 output texels x 4 q-slots = 128 uint4 stores
    for (int i = tid; i < 128; i += 256) {
        int to = i >> 2, q = i & 3;
        int t00 = 2 * to, t10 = 64 + 2 * to;
        float a[8];
#pragma unroll
        for (int j = 0; j < 8; j++) {
            int c = 8 * q + j;
            a[j] = 0.25f * (s[c * 129 + t00] + s[c * 129 + t00 + 1] +
                            s[c * 129 + t10] + s[c * 129 + t10 + 1]);
        }
        __half2 h0 = __floats2half2_rn(a[0], a[1]);
        __half2 h1 = __floats2half2_rn(a[2], a[3]);
        __half2 h2 = __floats2half2_rn(a[4], a[5]);
        __half2 h3 = __floats2half2_rn(a[6], a[7]);
        uint4 o;
        o.x = *(unsigned*)&h0; o.y = *(unsigned*)&h1;
        o.z = *(unsigned*)&h2; o.w = *(unsigned*)&h3;
        ((uint4*)SCRATCH)[((unsigned)f * 65536 + (unsigned)(y0 >> 1) * 256 + (x0 >> 1) + to) * 4 + q] = o;
    }
}

// ---------------------------------------------------------------------------
// Pool item: level computed directly from level-1 (KxK box average).
// ---------------------------------------------------------------------------
template<int K>
__device__ __forceinline__ void pool_item(int rel, int Rout, unsigned dst) {
    int q = rel & 3;
    int t = rel >> 2;
    int f = t / (Rout * Rout);
    int rem = t - f * Rout * Rout;
    int oy = rem / Rout, ox = rem % Rout;
    const uint4* S4 = (const uint4*)SCRATCH;
    unsigned sb = (((unsigned)f * 256 + oy * K) * 256 + ox * K) * 4 + q;
    float a[8];
#pragma unroll
    for (int i = 0; i < 8; i++) a[i] = 0.f;
    for (int dy = 0; dy < K; dy++) {
#pragma unroll
        for (int dx = 0; dx < K; dx++) {
            uint4 hv = S4[sb + ((unsigned)dy * 256 + dx) * 4];
            const unsigned* p = &hv.x;
#pragma unroll
            for (int j = 0; j < 4; j++) {
                float2 fv = __half22float2(*(const __half2*)&p[j]);
                a[2 * j] += fv.x; a[2 * j + 1] += fv.y;
            }
        }
    }
    float sc = 1.f / (float)(K * K);
    __half2 h0 = __floats2half2_rn(a[0] * sc, a[1] * sc);
    __half2 h1 = __floats2half2_rn(a[2] * sc, a[3] * sc);
    __half2 h2 = __floats2half2_rn(a[4] * sc, a[5] * sc);
    __half2 h3 = __floats2half2_rn(a[6] * sc, a[7] * sc);
    uint4 o;
    o.x = *(unsigned*)&h0; o.y = *(unsigned*)&h1;
    o.z = *(unsigned*)&h2; o.w = *(unsigned*)&h3;
    ((uint4*)SCRATCH)[(dst + (unsigned)t) * 4 + q] = o;
}

// ---------------------------------------------------------------------------
// GGX filter tile for level li (16x16 texels). R11 body: vertical texel
// pairing, packed fp16 weight shfl, HFMA2 accumulate with fp32 row flush.
// ---------------------------------------------------------------------------
__device__ __forceinline__ void filter_tile(int li, int rel) {
    int R = 256 >> (li - 1) >> 1;   // 256>>li ... keep simple:
    R = 256 >> (li - 1); R >>= 1; R = 256 >> li;   // R = 256>>li? level1 -> 256... wait
    R = 512 >> li;                  // level 1 -> 256, level 5 -> 16
    int nb = R >> 4;
    int f  = rel / (nb * nb);
    int r2 = rel - f * nb * nb;
    int y0 = (r2 / nb) * 16, x0 = (r2 % nb) * 16;
    unsigned inOff   = (unsigned)F_inOff[li];
    unsigned poolOff = (unsigned)F_poolOff[li];
    float a2   = F_a2[li];
    float a2m1 = a2 - 1.f;

    __shared__ uint4  hs[20 * 20 * 4];   // 25.6 KB halo data
    __shared__ float4 n3[20 * 20];       // 6.4 KB
    int tid = threadIdx.x;
    const uint4* S4 = (const uint4*)SCRATCH;
    float invR2 = 2.0f / (float)R;

    for (int i = tid; i < 1600; i += 256) {
        int t = i >> 2, q = i & 3;
        int hy = t / 20, hx = t - hy * 20;
        int gy = min(max(y0 - 2 + hy, 0), R - 1);
        int gx = min(max(x0 - 2 + hx, 0), R - 1);
        hs[i] = S4[(inOff + ((unsigned)f * R + gy) * R + gx) * 4 + q];
    }
    for (int i = tid; i < 400; i += 256) {
        int hy = i / 20, hx = i - hy * 20;
        int gy = min(max(y0 - 2 + hy, 0), R - 1);
        int gx = min(max(x0 - 2 + hx, 0), R - 1);
        float uu = (gx + 0.5f) * invR2 - 1.f;
        float vv = (gy + 0.5f) * invR2 - 1.f;
        float rn = rsqrtf(1.f + uu * uu + vv * vv);
        n3[i] = make_float4(rn, uu * rn, vv * rn, 0.f);
    }
    __syncthreads();

    int q   = tid & 3;
    int grp = tid >> 2;
    uint4* P4 = (uint4*)POOLH;

#pragma unroll
    for (int p = 0; p < 2; p++) {
        int pr = p * 64 + grp;
        int py = pr >> 4;
        int tx = pr & 15;
        int ty0 = py * 2;
        int gy0 = y0 + ty0, gx = x0 + tx;

        float u  = (gx + 0.5f) * invR2 - 1.f;
        float v0 = (gy0 + 0.5f) * invR2 - 1.f;
        float v1 = v0 + invR2;
        float rn00 = rsqrtf(1.f + u * u + v0 * v0);
        float rn01 = rsqrtf(1.f + u * u + v1 * v1);

        unsigned pk[8];
        float ws0 = 0.f, ws1 = 0.f;
#pragma unroll
        for (int k = 0; k < 8; k++) {
            int np = 4 * k + q;
            float w0 = 0.f, w1 = 0.f;
            if (np < 30) {
                int rp = np / 5, cp = np - rp * 5;
                float4 nn = n3[(ty0 + rp) * 20 + (tx + cp)];
                float base = nn.x + u * nn.y;
                if (np < 25) {
                    float cs = fminf(fmaf(v0, nn.z, base) * rn00, 1.f);
                    float dn = fmaf(cs * cs, a2m1, 1.f);
                    w0 = __fdividef(a2, dn * dn);
                }
                if (np >= 5) {
                    float cs = fminf(fmaf(v1, nn.z, base) * rn01, 1.f);
                    float dn = fmaf(cs * cs, a2m1, 1.f);
                    w1 = __fdividef(a2, dn * dn);
                }
            }
            __half2 hp = __floats2half2_rn(w0, w1);
            pk[k] = *(unsigned*)&hp;
            float2 bq = __half22float2(hp);
            ws0 += bq.x; ws1 += bq.y;
        }
        ws0 += __shfl_xor_sync(0xffffffffu, ws0, 1, 4);
        ws0 += __shfl_xor_sync(0xffffffffu, ws0, 2, 4);
        ws1 += __shfl_xor_sync(0xffffffffu, ws1, 1, 4);
        ws1 += __shfl_xor_sync(0xffffffffu, ws1, 2, 4);
        float i0 = __fdividef(1.f, fmaxf(ws0, 1e-8f));
        float i1 = __fdividef(1.f, fmaxf(ws1, 1e-8f));

        float f0[8], f1[8];
#pragma unroll
        for (int i = 0; i < 8; i++) { f0[i] = 0.f; f1[i] = 0.f; }

#pragma unroll
        for (int r = 0; r < 6; r++) {
            __half2 z = __float2half2_rn(0.f);
            __half2 a0[4] = {z, z, z, z};
            __half2 a1[4] = {z, z, z, z};
#pragma unroll
            for (int m = 0; m < 5; m++) {
                int np = r * 5 + m;
                unsigned wg = __shfl_sync(0xffffffffu, pk[np >> 2], np & 3, 4);
                __half2 wp = *(__half2*)&wg;
                uint4 hv = hs[((ty0 + r) * 20 + tx + m) * 4 + q];
                const __half2* pp = (const __half2*)&hv;
                if (r < 5) {
                    __half2 wh0 = __half2half2(__low2half(wp));
                    a0[0] = __hfma2(wh0, pp[0], a0[0]);
                    a0[1] = __hfma2(wh0, pp[1], a0[1]);
                    a0[2] = __hfma2(wh0, pp[2], a0[2]);
                    a0[3] = __hfma2(wh0, pp[3], a0[3]);
                }
                if (r >= 1) {
                    __half2 wh1 = __half2half2(__high2half(wp));
                    a1[0] = __hfma2(wh1, pp[0], a1[0]);
                    a1[1] = __hfma2(wh1, pp[1], a1[1]);
                    a1[2] = __hfma2(wh1, pp[2], a1[2]);
                    a1[3] = __hfma2(wh1, pp[3], a1[3]);
                }
            }
            if (r < 5) {
#pragma unroll
                for (int j = 0; j < 4; j++) {
                    float2 fv = __half22float2(a0[j]);
                    f0[2 * j] += fv.x; f0[2 * j + 1] += fv.y;
                }
            }
            if (r >= 1) {
#pragma unroll
                for (int j = 0; j < 4; j++) {
                    float2 fv = __half22float2(a1[j]);
                    f1[2 * j] += fv.x; f1[2 * j + 1] += fv.y;
                }
            }
        }

        unsigned ob = ((unsigned)f * TOTAL + poolOff + (unsigned)gy0 * R + gx) * 4 + q;
        {
            __half2 h0 = __floats2half2_rn(f0[0] * i0, f0[1] * i0);
            __half2 h1 = __floats2half2_rn(f0[2] * i0, f0[3] * i0);
            __half2 h2 = __floats2half2_rn(f0[4] * i0, f0[5] * i0);
            __half2 h3 = __floats2half2_rn(f0[6] * i0, f0[7] * i0);
            uint4 o;
            o.x = *(unsigned*)&h0; o.y = *(unsigned*)&h1;
            o.z = *(unsigned*)&h2; o.w = *(unsigned*)&h3;
            P4[ob] = o;
        }
        {
            __half2 h0 = __floats2half2_rn(f1[0] * i1, f1[1] * i1);
            __half2 h1 = __floats2half2_rn(f1[2] * i1, f1[3] * i1);
            __half2 h2 = __floats2half2_rn(f1[4] * i1, f1[5] * i1);
            __half2 h3 = __floats2half2_rn(f1[6] * i1, f1[7] * i1);
            uint4 o;
            o.x = *(unsigned*)&h0; o.y = *(unsigned*)&h1;
            o.z = *(unsigned*)&h2; o.w = *(unsigned*)&h3;
            P4[ob + (unsigned)R * 4] = o;
        }
    }
}

// ---------------------------------------------------------------------------
// K2: pool cascade (2040 blocks) + filter level-1 (1536 blocks) in ONE launch.
// Filter-L1 depends only on scratch L1 (from transpose), so the latency-bound
// pool cascade hides under the filter-L1 wave. Pool blocks scheduled first.
// ---------------------------------------------------------------------------
__global__ void __launch_bounds__(256) k_pool_filter1() {
    int bid = blockIdx.x;
    if (bid < 2040) {
        int idx = bid * 256 + threadIdx.x;
        if (idx < 6144)        pool_item<16>(idx,          16, 522240u);
        else if (idx < 30720)  pool_item<8> (idx - 6144,   32, 516096u);
        else if (idx < 129024) pool_item<4> (idx - 30720,  64, 491520u);
        else                   pool_item<2> (idx - 129024, 128, 393216u);
    } else {
        filter_tile(1, bid - 2040);
    }
}

// ---------------------------------------------------------------------------
// K3: filter levels 2..5 (510 blocks) — needs pool outputs.
// starts: lvl2: 0..383 (nb=8 -> 64/face), lvl3: 384..479, lvl4: 480..503, lvl5: 504..509
// ---------------------------------------------------------------------------
__global__ void __launch_bounds__(256) k_filter_rest() {
    int bid = blockIdx.x;
    if (bid < 384)      filter_tile(2, bid);
    else if (bid < 480) filter_tile(3, bid - 384);
    else if (bid < 504) filter_tile(4, bid - 480);
    else                filter_tile(5, bid - 504);
}

// ---------------------------------------------------------------------------
// Fetch: 4 lanes per query, 32-bit indexing throughout.
// ---------------------------------------------------------------------------
__global__ void k_fetch(const float* __restrict__ w, const float* __restrict__ rr,
                        float* __restrict__ out, int B) {
    long g = (long)blockIdx.x * 256 + threadIdx.x;
    if (g >= (long)B * 4) return;
    int b = (int)(g >> 2), q = (int)(g & 3);

    float dx = w[b * 3 + 0] * 2.f - 1.f;
    float dy = w[b * 3 + 1] * 2.f - 1.f;
    float dz = w[b * 3 + 2] * 2.f - 1.f;
    float ax = fabsf(dx), ay = fabsf(dy), az = fabsf(dz);
    bool cx = (ax >= ay) && (ax >= az);
    bool cy = (ay >= az) && !cx;
    float ma = cx ? ax : (cy ? ay : az);
    int face = cx ? (dx > 0.f ? 0 : 1) : (cy ? (dy > 0.f ? 2 : 3) : (dz > 0.f ? 4 : 5));
    float un = cx ? (dx > 0.f ? -dz : dz) : (cy ? dx : (dz > 0.f ? dx : -dx));
    float vn = cx ? -dy : (cy ? (dy > 0.f ? dz : -dz) : -dy);
    float inv = 1.f / ma;
    float u01 = (un * inv + 1.f) * 0.5f;
    float v01 = (vn * inv + 1.f) * 0.5f;

    float lev = fminf(fmaxf((rr[b] - 0.03f) * (1.f / 0.96f), 0.f), 1.f) * 5.f;
    int l0 = (int)lev;
    if (l0 > 5) l0 = 5;
    float t = lev - (float)l0;
    int l1 = min(l0 + 1, 5);

    const uint4* P4 = (const uint4*)POOLH;
    unsigned fb = (unsigned)face * TOTAL;
    float acc[8];
#pragma unroll
    for (int k = 0; k < 8; k++) acc[k] = 0.f;

#pragma unroll
    for (int s = 0; s < 2; s++) {
        int l = s ? l1 : l0;
        float wl = s ? t : (1.f - t);
        int res = 512 >> l;
        float rf = (float)res;
        float x = fminf(fmaxf(u01 * rf - 0.5f, 0.f), rf - 1.f);
        float y = fminf(fmaxf(v01 * rf - 0.5f, 0.f), rf - 1.f);
        int x0 = (int)x, y0 = (int)y;
        int x1 = min(x0 + 1, res - 1), y1 = min(y0 + 1, res - 1);
        float fx = x - (float)x0, fy = y - (float)y0;
        unsigned base = fb + (unsigned)d_offs[l];
        unsigned r0 = (base + (unsigned)y0 * res) * 4 + q;
        unsigned r1 = (base + (unsigned)y1 * res) * 4 + q;
        uint4 g00 = P4[r0 + (unsigned)x0 * 4];
        uint4 g01 = P4[r0 + (unsigned)x1 * 4];
        uint4 g10 = P4[r1 + (unsigned)x0 * 4];
        uint4 g11 = P4[r1 + (unsigned)x1 * 4];
        float w00 = wl * (1.f - fx) * (1.f - fy);
        float w01 = wl * fx * (1.f - fy);
        float w10 = wl * (1.f - fx) * fy;
        float w11 = wl * fx * fy;
        const unsigned* p00 = &g00.x; const unsigned* p01 = &g01.x;
        const unsigned* p10 = &g10.x; const unsigned* p11 = &g11.x;
#pragma unroll
        for (int k = 0; k < 4; k++) {
            float2 f00 = __half22float2(*(const __half2*)&p00[k]);
            float2 f01 = __half22float2(*(const __half2*)&p01[k]);
            float2 f10 = __half22float2(*(const __half2*)&p10[k]);
            float2 f11 = __half22float2(*(const __half2*)&p11[k]);
            acc[2 * k]     += w00 * f00.x + w01 * f01.x + w10 * f10.x + w11 * f11.x;
            acc[2 * k + 1] += w00 * f00.y + w01 * f01.y + w10 * f10.y + w11 * f11.y;
        }
    }
    float4* o4 = (float4*)&out[(unsigned)b * 32 + q * 8];
    o4[0] = make_float4(acc[0], acc[1], acc[2], acc[3]);
    o4[1] = make_float4(acc[4], acc[5], acc[6], acc[7]);
}

extern "C" void kernel_launch(void* const* d_in, const int* in_sizes, int n_in,
                              void* d_out, int out_size) {
    const float* feat = (const float*)d_in[0];
    const float* w    = (const float*)d_in[1];
    const float* r    = (const float*)d_in[2];
    float* out = (float*)d_out;
    int B = in_sizes[2];

    k_transpose_pool1<<<dim3(8, 256, 6), 256>>>(feat);
    k_pool_filter1<<<2040 + 1536, 256>>>();
    k_filter_rest<<<510, 256>>>();

    long nthreads = (long)B * 4;
    k_fetch<<<(unsigned)((nthreads + 255) / 256), 256>>>(w, r, out, B);
}

// round 15
// speedup vs baseline: 1.6800x; 1.0409x over previous
#include <cuda_runtime.h>
#include <cuda_fp16.h>

#define NC 32
#define NLEV 6
#define TOTAL 349440   // sum of res^2 over 6 levels

// Pool: [face][texel(level-major)][channel], HALF, 134 MB
__device__ __half POOLH[6ll * TOTAL * NC];
// Scratch: unfiltered pooled levels 1..5, channel-last HALF. 33.5 MB
__device__ __half SCRATCH[523776ll * NC];

__constant__ int d_offs[NLEV] = {0, 262144, 327680, 344064, 348160, 349184};

// Per-level filter tables (levels 1..5)
__constant__ int   F_inOff[6]  = {0, 0, 393216, 491520, 516096, 522240};   // index by level
__constant__ int   F_poolOff[6]= {0, 262144, 327680, 344064, 348160, 349184};
__constant__ float F_a2[6]     = {0.f, 0.00243101246f, 0.030233088f, 0.137822329f, 0.419904f, 0.96059601f}; // rough^4

// ---------------------------------------------------------------------------
// K1: transpose feature (C,6,512,512) -> pool level0 (half, channel-last)
//     AND compute level-1 avg-pool into SCRATCH (half, vectorized store)
// ---------------------------------------------------------------------------
__global__ void k_transpose_pool1(const float* __restrict__ feat) {
    int f = blockIdx.z;
    int x0 = blockIdx.x * 64;
    int y0 = blockIdx.y * 2;
    __shared__ float s[32 * 129];
    int tid = threadIdx.x;

    for (int i = tid; i < 32 * 32; i += 256) {
        int c = i >> 5, v = i & 31;
        int t0 = v * 4;
        int yy = y0 + (t0 >> 6), xx = x0 + (t0 & 63);
        float4 d = *(const float4*)&feat[(((size_t)c * 6 + f) * 512 + yy) * 512 + xx];
        s[c * 129 + t0 + 0] = d.x;
        s[c * 129 + t0 + 1] = d.y;
        s[c * 129 + t0 + 2] = d.z;
        s[c * 129 + t0 + 3] = d.w;
    }
    __syncthreads();

    uint4* P4 = (uint4*)POOLH;   // one uint4 = 8 half channels
    for (int i = tid; i < 512; i += 256) {
        int t = i >> 2, q = i & 3;
        int yy = y0 + (t >> 6), xx = x0 + (t & 63);
        const float* sp = &s[(8 * q) * 129 + t];
        __half2 h0 = __floats2half2_rn(sp[0],       sp[129]);
        __half2 h1 = __floats2half2_rn(sp[2 * 129], sp[3 * 129]);
        __half2 h2 = __floats2half2_rn(sp[4 * 129], sp[5 * 129]);
        __half2 h3 = __floats2half2_rn(sp[6 * 129], sp[7 * 129]);
        uint4 o;
        o.x = *(unsigned*)&h0; o.y = *(unsigned*)&h1;
        o.z = *(unsigned*)&h2; o.w = *(unsigned*)&h3;
        P4[((unsigned)f * TOTAL + (unsigned)yy * 512 + xx) * 4 + q] = o;
    }
    // level-1 pool: 32 output texels x 4 q-slots = 128 uint4 stores
    for (int i = tid; i < 128; i += 256) {
        int to = i >> 2, q = i & 3;
        int t00 = 2 * to, t10 = 64 + 2 * to;
        float a[8];
#pragma unroll
        for (int j = 0; j < 8; j++) {
            int c = 8 * q + j;
            a[j] = 0.25f * (s[c * 129 + t00] + s[c * 129 + t00 + 1] +
                            s[c * 129 + t10] + s[c * 129 + t10 + 1]);
        }
        __half2 h0 = __floats2half2_rn(a[0], a[1]);
        __half2 h1 = __floats2half2_rn(a[2], a[3]);
        __half2 h2 = __floats2half2_rn(a[4], a[5]);
        __half2 h3 = __floats2half2_rn(a[6], a[7]);
        uint4 o;
        o.x = *(unsigned*)&h0; o.y = *(unsigned*)&h1;
        o.z = *(unsigned*)&h2; o.w = *(unsigned*)&h3;
        ((uint4*)SCRATCH)[((unsigned)f * 65536 + (unsigned)(y0 >> 1) * 256 + (x0 >> 1) + to) * 4 + q] = o;
    }
}

// ---------------------------------------------------------------------------
// 2x2 average of four 8-half uint4 vectors (fp32 math, one fp16 rounding)
// ---------------------------------------------------------------------------
__device__ __forceinline__ uint4 avg4(uint4 A, uint4 B, uint4 C, uint4 D) {
    const unsigned* pa = &A.x; const unsigned* pb = &B.x;
    const unsigned* pc = &C.x; const unsigned* pd = &D.x;
    uint4 o;
    unsigned* po = &o.x;
#pragma unroll
    for (int j = 0; j < 4; j++) {
        float2 fa = __half22float2(*(const __half2*)&pa[j]);
        float2 fb = __half22float2(*(const __half2*)&pb[j]);
        float2 fc = __half22float2(*(const __half2*)&pc[j]);
        float2 fd = __half22float2(*(const __half2*)&pd[j]);
        __half2 h = __floats2half2_rn(0.25f * (fa.x + fb.x + fc.x + fd.x),
                                      0.25f * (fa.y + fb.y + fc.y + fd.y));
        po[j] = *(unsigned*)&h;
    }
    return o;
}

// ---------------------------------------------------------------------------
// Hierarchical pool: one block = 32x32 L1 region of one face.
// Computes L2 (16x16), L3 (8x8), L4 (4x4), L5 (2x2) through smem ladder.
// Reads L1 ONCE (25 MB total vs 100 MB for direct-from-L1 per level).
// ---------------------------------------------------------------------------
__device__ __forceinline__ void pool_hier(int rel, char* buf) {
    uint4* s2 = (uint4*)buf;            // 16*16*4 uint4 = 16 KB
    uint4* s3 = (uint4*)(buf + 16384);  // 8*8*4  uint4 = 4 KB
    uint4* s4 = (uint4*)(buf + 20480);  // 4*4*4  uint4 = 1 KB
    int f   = rel >> 6;
    int sub = rel & 63;
    int by = sub >> 3, bx = sub & 7;    // region origin (by*32, bx*32) in L1
    int tid = threadIdx.x;
    const uint4* S4 = (const uint4*)SCRATCH;
    uint4* G4 = (uint4*)SCRATCH;

    // L2: 16x16 x 4q = 1024 items
    for (int i = tid; i < 1024; i += 256) {
        int q = i & 3, t = i >> 2;
        int ty = t >> 4, tx = t & 15;
        int gy = by * 32 + 2 * ty, gx = bx * 32 + 2 * tx;
        unsigned sb = (((unsigned)f * 256 + gy) * 256 + gx) * 4 + q;
        uint4 o = avg4(S4[sb], S4[sb + 4], S4[sb + 1024], S4[sb + 1028]);
        s2[t * 4 + q] = o;
        unsigned Y = by * 16 + ty, X = bx * 16 + tx;
        G4[(393216u + (unsigned)f * 16384 + Y * 128 + X) * 4 + q] = o;
    }
    __syncthreads();

    // L3: 8x8 x 4q = 256 items (exactly one per thread)
    {
        int q = tid & 3, t = tid >> 2;
        int ty = t >> 3, tx = t & 7;
        int b0 = ((2 * ty) * 16 + 2 * tx) * 4 + q;
        uint4 o = avg4(s2[b0], s2[b0 + 4], s2[b0 + 64], s2[b0 + 68]);
        s3[t * 4 + q] = o;
        unsigned Y = by * 8 + ty, X = bx * 8 + tx;
        G4[(491520u + (unsigned)f * 4096 + Y * 64 + X) * 4 + q] = o;
    }
    __syncthreads();

    // L4: 4x4 x 4q = 64 items
    if (tid < 64) {
        int q = tid & 3, t = tid >> 2;
        int ty = t >> 2, tx = t & 3;
        int b0 = ((2 * ty) * 8 + 2 * tx) * 4 + q;
        uint4 o = avg4(s3[b0], s3[b0 + 4], s3[b0 + 32], s3[b0 + 36]);
        s4[t * 4 + q] = o;
        unsigned Y = by * 4 + ty, X = bx * 4 + tx;
        G4[(516096u + (unsigned)f * 1024 + Y * 32 + X) * 4 + q] = o;
    }
    __syncthreads();

    // L5: 2x2 x 4q = 16 items
    if (tid < 16) {
        int q = tid & 3, t = tid >> 2;
        int ty = t >> 1, tx = t & 1;
        int b0 = ((2 * ty) * 4 + 2 * tx) * 4 + q;
        uint4 o = avg4(s4[b0], s4[b0 + 4], s4[b0 + 16], s4[b0 + 20]);
        unsigned Y = by * 2 + ty, X = bx * 2 + tx;
        G4[(522240u + (unsigned)f * 256 + Y * 16 + X) * 4 + q] = o;
    }
}

// ---------------------------------------------------------------------------
// GGX filter tile (16x16 texels). Vertical texel pairing, packed fp16 weight
// shfl, HFMA2 accumulate with fp32 row flush. buf: 32000 B shared.
// ---------------------------------------------------------------------------
__device__ __forceinline__ void filter_tile(int li, int rel, char* buf) {
    int R = 512 >> li;                  // level 1 -> 256 ... level 5 -> 16
    int nb = R >> 4;
    int f  = rel / (nb * nb);
    int r2 = rel - f * nb * nb;
    int y0 = (r2 / nb) * 16, x0 = (r2 % nb) * 16;
    unsigned inOff   = (unsigned)F_inOff[li];
    unsigned poolOff = (unsigned)F_poolOff[li];
    float a2   = F_a2[li];
    float a2m1 = a2 - 1.f;

    uint4*  hs = (uint4*)buf;             // 20*20*4 = 25600 B
    float4* n3 = (float4*)(buf + 25600);  // 400*16  = 6400 B
    int tid = threadIdx.x;
    const uint4* S4 = (const uint4*)SCRATCH;
    float invR2 = 2.0f / (float)R;

    for (int i = tid; i < 1600; i += 256) {
        int t = i >> 2, q = i & 3;
        int hy = t / 20, hx = t - hy * 20;
        int gy = min(max(y0 - 2 + hy, 0), R - 1);
        int gx = min(max(x0 - 2 + hx, 0), R - 1);
        hs[i] = S4[(inOff + ((unsigned)f * R + gy) * R + gx) * 4 + q];
    }
    for (int i = tid; i < 400; i += 256) {
        int hy = i / 20, hx = i - hy * 20;
        int gy = min(max(y0 - 2 + hy, 0), R - 1);
        int gx = min(max(x0 - 2 + hx, 0), R - 1);
        float uu = (gx + 0.5f) * invR2 - 1.f;
        float vv = (gy + 0.5f) * invR2 - 1.f;
        float rn = rsqrtf(1.f + uu * uu + vv * vv);
        n3[i] = make_float4(rn, uu * rn, vv * rn, 0.f);
    }
    __syncthreads();

    int q   = tid & 3;
    int grp = tid >> 2;
    uint4* P4 = (uint4*)POOLH;

#pragma unroll
    for (int p = 0; p < 2; p++) {
        int pr = p * 64 + grp;
        int py = pr >> 4;
        int tx = pr & 15;
        int ty0 = py * 2;
        int gy0 = y0 + ty0, gx = x0 + tx;

        float u  = (gx + 0.5f) * invR2 - 1.f;
        float v0 = (gy0 + 0.5f) * invR2 - 1.f;
        float v1 = v0 + invR2;
        float rn00 = rsqrtf(1.f + u * u + v0 * v0);
        float rn01 = rsqrtf(1.f + u * u + v1 * v1);

        unsigned pk[8];
        float ws0 = 0.f, ws1 = 0.f;
#pragma unroll
        for (int k = 0; k < 8; k++) {
            int np = 4 * k + q;
            float w0 = 0.f, w1 = 0.f;
            if (np < 30) {
                int rp = np / 5, cp = np - rp * 5;
                float4 nn = n3[(ty0 + rp) * 20 + (tx + cp)];
                float base = nn.x + u * nn.y;
                if (np < 25) {
                    float cs = fminf(fmaf(v0, nn.z, base) * rn00, 1.f);
                    float dn = fmaf(cs * cs, a2m1, 1.f);
                    w0 = __fdividef(a2, dn * dn);
                }
                if (np >= 5) {
                    float cs = fminf(fmaf(v1, nn.z, base) * rn01, 1.f);
                    float dn = fmaf(cs * cs, a2m1, 1.f);
                    w1 = __fdividef(a2, dn * dn);
                }
            }
            __half2 hp = __floats2half2_rn(w0, w1);
            pk[k] = *(unsigned*)&hp;
            float2 bq = __half22float2(hp);
            ws0 += bq.x; ws1 += bq.y;
        }
        ws0 += __shfl_xor_sync(0xffffffffu, ws0, 1, 4);
        ws0 += __shfl_xor_sync(0xffffffffu, ws0, 2, 4);
        ws1 += __shfl_xor_sync(0xffffffffu, ws1, 1, 4);
        ws1 += __shfl_xor_sync(0xffffffffu, ws1, 2, 4);
        float i0 = __fdividef(1.f, fmaxf(ws0, 1e-8f));
        float i1 = __fdividef(1.f, fmaxf(ws1, 1e-8f));

        float f0[8], f1[8];
#pragma unroll
        for (int i = 0; i < 8; i++) { f0[i] = 0.f; f1[i] = 0.f; }

#pragma unroll
        for (int r = 0; r < 6; r++) {
            __half2 z = __float2half2_rn(0.f);
            __half2 a0[4] = {z, z, z, z};
            __half2 a1[4] = {z, z, z, z};
#pragma unroll
            for (int m = 0; m < 5; m++) {
                int np = r * 5 + m;
                unsigned wg = __shfl_sync(0xffffffffu, pk[np >> 2], np & 3, 4);
                __half2 wp = *(__half2*)&wg;
                uint4 hv = hs[((ty0 + r) * 20 + tx + m) * 4 + q];
                const __half2* pp = (const __half2*)&hv;
                if (r < 5) {
                    __half2 wh0 = __half2half2(__low2half(wp));
                    a0[0] = __hfma2(wh0, pp[0], a0[0]);
                    a0[1] = __hfma2(wh0, pp[1], a0[1]);
                    a0[2] = __hfma2(wh0, pp[2], a0[2]);
                    a0[3] = __hfma2(wh0, pp[3], a0[3]);
                }
                if (r >= 1) {
                    __half2 wh1 = __half2half2(__high2half(wp));
                    a1[0] = __hfma2(wh1, pp[0], a1[0]);
                    a1[1] = __hfma2(wh1, pp[1], a1[1]);
                    a1[2] = __hfma2(wh1, pp[2], a1[2]);
                    a1[3] = __hfma2(wh1, pp[3], a1[3]);
                }
            }
            if (r < 5) {
#pragma unroll
                for (int j = 0; j < 4; j++) {
                    float2 fv = __half22float2(a0[j]);
                    f0[2 * j] += fv.x; f0[2 * j + 1] += fv.y;
                }
            }
            if (r >= 1) {
#pragma unroll
                for (int j = 0; j < 4; j++) {
                    float2 fv = __half22float2(a1[j]);
                    f1[2 * j] += fv.x; f1[2 * j + 1] += fv.y;
                }
            }
        }

        unsigned ob = ((unsigned)f * TOTAL + poolOff + (unsigned)gy0 * R + gx) * 4 + q;
        {
            __half2 h0 = __floats2half2_rn(f0[0] * i0, f0[1] * i0);
            __half2 h1 = __floats2half2_rn(f0[2] * i0, f0[3] * i0);
            __half2 h2 = __floats2half2_rn(f0[4] * i0, f0[5] * i0);
            __half2 h3 = __floats2half2_rn(f0[6] * i0, f0[7] * i0);
            uint4 o;
            o.x = *(unsigned*)&h0; o.y = *(unsigned*)&h1;
            o.z = *(unsigned*)&h2; o.w = *(unsigned*)&h3;
            P4[ob] = o;
        }
        {
            __half2 h0 = __floats2half2_rn(f1[0] * i1, f1[1] * i1);
            __half2 h1 = __floats2half2_rn(f1[2] * i1, f1[3] * i1);
            __half2 h2 = __floats2half2_rn(f1[4] * i1, f1[5] * i1);
            __half2 h3 = __floats2half2_rn(f1[6] * i1, f1[7] * i1);
            uint4 o;
            o.x = *(unsigned*)&h0; o.y = *(unsigned*)&h1;
            o.z = *(unsigned*)&h2; o.w = *(unsigned*)&h3;
            P4[ob + (unsigned)R * 4] = o;
        }
    }
}

// ---------------------------------------------------------------------------
// K2: hierarchical pool (384 blocks) + filter level-1 (1536 blocks), one launch.
// Filter-L1 depends only on scratch L1 (from transpose); pool hides under it.
// ---------------------------------------------------------------------------
__global__ void __launch_bounds__(256) k_pool_filter1() {
    __shared__ __align__(16) char buf[32000];
    int bid = blockIdx.x;
    if (bid < 384) pool_hier(bid, buf);
    else           filter_tile(1, bid - 384, buf);
}

// ---------------------------------------------------------------------------
// K3: filter levels 2..5 (510 blocks) — needs pool outputs.
// ---------------------------------------------------------------------------
__global__ void __launch_bounds__(256) k_filter_rest() {
    __shared__ __align__(16) char buf[32000];
    int bid = blockIdx.x;
    if (bid < 384)      filter_tile(2, bid, buf);
    else if (bid < 480) filter_tile(3, bid - 384, buf);
    else if (bid < 504) filter_tile(4, bid - 480, buf);
    else                filter_tile(5, bid - 504, buf);
}

// ---------------------------------------------------------------------------
// Fetch: 4 lanes per query, 32-bit indexing throughout.
// ---------------------------------------------------------------------------
__global__ void k_fetch(const float* __restrict__ w, const float* __restrict__ rr,
                        float* __restrict__ out, int B) {
    long g = (long)blockIdx.x * 256 + threadIdx.x;
    if (g >= (long)B * 4) return;
    int b = (int)(g >> 2), q = (int)(g & 3);

    float dx = w[b * 3 + 0] * 2.f - 1.f;
    float dy = w[b * 3 + 1] * 2.f - 1.f;
    float dz = w[b * 3 + 2] * 2.f - 1.f;
    float ax = fabsf(dx), ay = fabsf(dy), az = fabsf(dz);
    bool cx = (ax >= ay) && (ax >= az);
    bool cy = (ay >= az) && !cx;
    float ma = cx ? ax : (cy ? ay : az);
    int face = cx ? (dx > 0.f ? 0 : 1) : (cy ? (dy > 0.f ? 2 : 3) : (dz > 0.f ? 4 : 5));
    float un = cx ? (dx > 0.f ? -dz : dz) : (cy ? dx : (dz > 0.f ? dx : -dx));
    float vn = cx ? -dy : (cy ? (dy > 0.f ? dz : -dz) : -dy);
    float inv = 1.f / ma;
    float u01 = (un * inv + 1.f) * 0.5f;
    float v01 = (vn * inv + 1.f) * 0.5f;

    float lev = fminf(fmaxf((rr[b] - 0.03f) * (1.f / 0.96f), 0.f), 1.f) * 5.f;
    int l0 = (int)lev;
    if (l0 > 5) l0 = 5;
    float t = lev - (float)l0;
    int l1 = min(l0 + 1, 5);

    const uint4* P4 = (const uint4*)POOLH;
    unsigned fb = (unsigned)face * TOTAL;
    float acc[8];
#pragma unroll
    for (int k = 0; k < 8; k++) acc[k] = 0.f;

#pragma unroll
    for (int s = 0; s < 2; s++) {
        int l = s ? l1 : l0;
        float wl = s ? t : (1.f - t);
        int res = 512 >> l;
        float rf = (float)res;
        float x = fminf(fmaxf(u01 * rf - 0.5f, 0.f), rf - 1.f);
        float y = fminf(fmaxf(v01 * rf - 0.5f, 0.f), rf - 1.f);
        int x0 = (int)x, y0 = (int)y;
        int x1 = min(x0 + 1, res - 1), y1 = min(y0 + 1, res - 1);
        float fx = x - (float)x0, fy = y - (float)y0;
        unsigned base = fb + (unsigned)d_offs[l];
        unsigned r0 = (base + (unsigned)y0 * res) * 4 + q;
        unsigned r1 = (base + (unsigned)y1 * res) * 4 + q;
        uint4 g00 = P4[r0 + (unsigned)x0 * 4];
        uint4 g01 = P4[r0 + (unsigned)x1 * 4];
        uint4 g10 = P4[r1 + (unsigned)x0 * 4];
        uint4 g11 = P4[r1 + (unsigned)x1 * 4];
        float w00 = wl * (1.f - fx) * (1.f - fy);
        float w01 = wl * fx * (1.f - fy);
        float w10 = wl * (1.f - fx) * fy;
        float w11 = wl * fx * fy;
        const unsigned* p00 = &g00.x; const unsigned* p01 = &g01.x;
        const unsigned* p10 = &g10.x; const unsigned* p11 = &g11.x;
#pragma unroll
        for (int k = 0; k < 4; k++) {
            float2 f00 = __half22float2(*(const __half2*)&p00[k]);
            float2 f01 = __half22float2(*(const __half2*)&p01[k]);
            float2 f10 = __half22float2(*(const __half2*)&p10[k]);
            float2 f11 = __half22float2(*(const __half2*)&p11[k]);
            acc[2 * k]     += w00 * f00.x + w01 * f01.x + w10 * f10.x + w11 * f11.x;
            acc[2 * k + 1] += w00 * f00.y + w01 * f01.y + w10 * f10.y + w11 * f11.y;
        }
    }
    float4* o4 = (float4*)&out[(unsigned)b * 32 + q * 8];
    o4[0] = make_float4(acc[0], acc[1], acc[2], acc[3]);
    o4[1] = make_float4(acc[4], acc[5], acc[6], acc[7]);
}

extern "C" void kernel_launch(void* const* d_in, const int* in_sizes, int n_in,
                              void* d_out, int out_size) {
    const float* feat = (const float*)d_in[0];
    const float* w    = (const float*)d_in[1];
    const float* r    = (const float*)d_in[2];
    float* out = (float*)d_out;
    int B = in_sizes[2];

    k_transpose_pool1<<<dim3(8, 256, 6), 256>>>(feat);
    k_pool_filter1<<<384 + 1536, 256>>>();
    k_filter_rest<<<510, 256>>>();

    long nthreads = (long)B * 4;
    k_fetch<<<(unsigned)((nthreads + 255) / 256), 256>>>(w, r, out, B);
}